// round 12
// baseline (speedup 1.0000x reference)
#include <cuda_runtime.h>
#include <cuda_bf16.h>

// Problem constants
#define BB    16
#define MM    127
#define PP    3
#define KLEN  132
#define NSPAN 126
#define SS    256
#define CDIM  3
#define EPSF  1e-8f

#define EVT 256      // threads per block
#define GPB 8        // iu per block
#define VPB 128      // iv per block (v-split)

// ---------------------------------------------------------------------------
// Warp-collective knot prep (proven R5/R7 numerics).
// ---------------------------------------------------------------------------
__device__ __forceinline__ void scan_knots_warp(const float* __restrict__ knots,
                                                float* __restrict__ sK,
                                                int lane)
{
    float vals[5];
    float run = 0.f;
    #pragma unroll
    for (int k = 0; k < 5; k++) {
        const int idx = lane * 5 + k;
        if (idx < KLEN) {
            float w = knots[idx];
            run += (w < 0.f) ? 1e-4f : w;
            vals[k] = run;
        }
    }
    float tot = run;
    #pragma unroll
    for (int off = 1; off < 32; off <<= 1) {
        float n = __shfl_up_sync(0xFFFFFFFFu, tot, off);
        if (lane >= off) tot += n;
    }
    const float pre = tot - run;                           // exclusive prefix
    const float k0   = __shfl_sync(0xFFFFFFFFu, vals[0], 0);
    const float kend = __shfl_sync(0xFFFFFFFFu, tot, 31);
    const float inv  = 1.f / (kend - k0);
    #pragma unroll
    for (int k = 0; k < 5; k++) {
        const int idx = lane * 5 + k;
        if (idx < KLEN) sK[idx] = (vals[k] + pre - k0) * inv;
    }
}

// ---------------------------------------------------------------------------
// Span (binary search == reference masked-argmin) + cubic basis,
// reference's exact FP expression order.
// ---------------------------------------------------------------------------
__device__ __forceinline__ void span_basis(const float* __restrict__ sK,
                                           float t, int* span_out, float4* n_out)
{
    int lo = -1, hi = NSPAN;
    while (hi - lo > 1) {
        const int mid = (lo + hi) >> 1;
        if (t - sK[3 + mid] > EPSF) lo = mid; else hi = mid;
    }
    int idx = (lo < 0) ? 0 : lo;
    int span = idx + PP;
    span = (span < PP) ? PP : (span > MM ? MM : span);

    float Ni[4];
    Ni[0] = 1.f; Ni[1] = 0.f; Ni[2] = 0.f; Ni[3] = 0.f;
    #pragma unroll
    for (int k = 1; k <= PP; k++) {
        float saved = 0.f;
        #pragma unroll
        for (int r = 0; r < 3; r++) {
            if (r >= k) break;
            const float K1 = sK[span + r + 1];
            const float K2 = sK[span + 1 - k + r];
            const float denom = (K1 - t) + (t - K2);   // exact ref order
            const float temp  = (denom == 0.f) ? 1e-4f : Ni[r] / denom;
            Ni[r] = saved + (K1 - t) * temp;
            saved = (t - K2) * temp;
        }
        Ni[k] = saved;
    }
    *span_out = span;
    *n_out = make_float4(Ni[0], Ni[1], Ni[2], Ni[3]);
}

// ---------------------------------------------------------------------------
// Fused kernel, v-split: one 256-thread block per (b, 8-iu group, v-half).
//  prep: warps 0/1 scan u/v knots; threads 0..127 compute their v-basis
//        (iv = vh + tid) while threads 128..135 compute the 8 u-bases.
//  main: 4 iterations; each contracts an iu PAIR (192 threads, 96 per iu)
//        with next-pair LDGs issued pre-barrier (double-buffered sT), then
//        stage 2 evaluates 256 points (2 iu x 128 iv, one per thread).
// ---------------------------------------------------------------------------
__global__ __launch_bounds__(EVT, 6) void fused_kernel(
    const float* __restrict__ ctrl,
    const float* __restrict__ knot_u,
    const float* __restrict__ knot_v,
    const float* __restrict__ uu,
    const float* __restrict__ vv,
    float* __restrict__ out)
{
    const int bid  = blockIdx.x;            // 0 .. 1023
    const int b    = bid >> 6;              // 64 blocks per batch
    const int rem  = bid & 63;
    const int iug  = (rem >> 1) * GPB;      // 32 iu-groups
    const int vh   = (rem & 1) * VPB;       // v-half offset
    const int tid  = threadIdx.x;
    const int wid  = tid >> 5;
    const int lane = tid & 31;

    __shared__ float  sKu[KLEN];
    __shared__ float  sKv[KLEN];
    __shared__ float4 s_nu[GPB];
    __shared__ int    s_us[GPB];
    __shared__ float4 s_nv[VPB];
    __shared__ int    s_voff[VPB];
    __shared__ float  sT[2][2][128 * CDIM]; // [buffer][iu-of-pair][row]

    // --- knot scans (two warps concurrent) ---
    if (wid == 0)      scan_knots_warp(knot_u + b * KLEN, sKu, lane);
    else if (wid == 1) scan_knots_warp(knot_v + b * KLEN, sKv, lane);
    __syncthreads();

    // --- bases: v on threads 0..127, u on threads 128..135 (concurrent) ---
    if (tid < VPB) {
        int vs; float4 nv;
        span_basis(sKv, vv[vh + tid], &vs, &nv);
        s_nv[tid]   = nv;
        s_voff[tid] = (vs - 3) * CDIM;
    } else if (tid < VPB + GPB) {
        const int g = tid - VPB;
        int us; float4 nu;
        span_basis(sKu, uu[iug + g], &us, &nu);
        s_nu[g] = nu;
        s_us[g] = us;
    }
    __syncthreads();

    // --- pipelined main loop over 4 iu-pairs ---
    const int owner = (tid >= 96);          // which iu of the pair (for tid<192)
    const int idx96 = tid - (owner ? 96 : 0);
    float4 r0, r1, r2, r3;

    if (tid < 192) {                        // prologue: loads for pair 0
        const float4* cb4 = (const float4*)(ctrl + (size_t)(b * 128 + (s_us[owner] - 3)) * 384);
        r0 = cb4[idx96]; r1 = cb4[idx96 + 96]; r2 = cb4[idx96 + 192]; r3 = cb4[idx96 + 288];
    }

    const int iu_loc = tid >> 7;            // stage-2: which iu of the pair
    const int iv_loc = tid & 127;
    const float4 nv   = s_nv[iv_loc];
    const int    voff = s_voff[iv_loc];

    #pragma unroll
    for (int g = 0; g < 4; g++) {
        const int p = g & 1;

        if (tid < 192) {
            const float4 q = s_nu[2 * g + owner];
            float4 acc;
            acc.x = q.x * r0.x + q.y * r1.x + q.z * r2.x + q.w * r3.x;
            acc.y = q.x * r0.y + q.y * r1.y + q.z * r2.y + q.w * r3.y;
            acc.z = q.x * r0.z + q.y * r1.z + q.z * r2.z + q.w * r3.z;
            acc.w = q.x * r0.w + q.y * r1.w + q.z * r2.w + q.w * r3.w;
            ((float4*)sT[p][owner])[idx96] = acc;

            if (g < 3) {                    // issue next pair's loads pre-barrier
                const float4* cb4 = (const float4*)(ctrl + (size_t)(b * 128 + (s_us[2 * g + 2 + owner] - 3)) * 384);
                r0 = cb4[idx96]; r1 = cb4[idx96 + 96]; r2 = cb4[idx96 + 192]; r3 = cb4[idx96 + 288];
            }
        }
        __syncthreads();

        // stage 2: one point per thread (iu = iug+2g+iu_loc, iv = vh+iv_loc)
        const float* t0 = sT[p][iu_loc] + voff;
        const float ax = nv.x * t0[0] + nv.y * t0[3] + nv.z * t0[6] + nv.w * t0[9];
        const float ay = nv.x * t0[1] + nv.y * t0[4] + nv.z * t0[7] + nv.w * t0[10];
        const float az = nv.x * t0[2] + nv.y * t0[5] + nv.z * t0[8] + nv.w * t0[11];
        const size_t o = (((size_t)b * SS + (iug + 2 * g + iu_loc)) * SS + (vh + iv_loc)) * CDIM;
        out[o] = ax; out[o + 1] = ay; out[o + 2] = az;
        // Double buffer + next iteration's barrier covers WAR on sT.
    }
}

// ---------------------------------------------------------------------------
// Inputs (metadata order): ctrl_pts, knot_u, knot_v, u, v. Output: float32.
// ---------------------------------------------------------------------------
extern "C" void kernel_launch(void* const* d_in, const int* in_sizes, int n_in,
                              void* d_out, int out_size)
{
    const float* ctrl   = (const float*)d_in[0];
    const float* knot_u = (const float*)d_in[1];
    const float* knot_v = (const float*)d_in[2];
    const float* uu     = (const float*)d_in[3];
    const float* vv     = (const float*)d_in[4];
    float* out = (float*)d_out;

    fused_kernel<<<BB * (SS / GPB) * (SS / VPB), EVT>>>(ctrl, knot_u, knot_v, uu, vv, out);
}